// round 2
// baseline (speedup 1.0000x reference)
#include <cuda_runtime.h>
#include <math.h>

// RoI Align pyramid (FPN). Inputs (metadata.txt order):
//   d_in[0] metadata [1,3] f32 (rows, cols, 1)
//   d_in[1] boxes    [1,1024,4] f32 (x1,y1,x2,y2)
//   d_in[2] p2 [1,256,256,256] f32
//   d_in[3] p3 [1,128,128,256] f32
//   d_in[4] p4 [1, 64, 64,256] f32
//   d_in[5] p5 [1, 32, 32,256] f32
// Output: [1,1024,7,7,256] f32
//
// One block per box, 256 threads. Threads split into 4 groups of 64;
// each group processes one (gy,gx) sample at a time, lane handles one
// float4 channel chunk (64 * float4 = 256 channels). All loads/stores
// are fully coalesced 128-bit accesses.

#define EXTENT 7
#define NBOX   1024
#define CH4    64   // 256 channels / 4

__global__ __launch_bounds__(256, 8)
void roi_align_pyramid_kernel(const float* __restrict__ metadata,
                              const float* __restrict__ boxes,
                              const float* __restrict__ p2,
                              const float* __restrict__ p3,
                              const float* __restrict__ p4,
                              const float* __restrict__ p5,
                              float* __restrict__ out)
{
    const int box = blockIdx.x;

    const float rows = metadata[0];
    const float cols = metadata[1];

    const float x1 = boxes[box * 4 + 0];
    const float y1 = boxes[box * 4 + 1];
    const float x2 = boxes[box * 4 + 2];
    const float y2 = boxes[box * 4 + 3];

    const float h = y2 - y1;
    const float w = x2 - x1;

    // roi_level = clip(4 + round(log(sqrt(h*w)/sqrt(rows*cols)) / log(2)), 2, 5)
    // jnp.round is round-half-to-even -> rintf.
    float rl = logf(sqrtf(h * w) / sqrtf(rows * cols)) * (1.0f / logf(2.0f));
    rl = fminf(5.0f, fmaxf(2.0f, 4.0f + rintf(rl)));
    const int lvl = (int)rl;  // 2..5

    const float* feat;
    int H;
    switch (lvl) {
        case 2: feat = p2; H = 256; break;
        case 3: feat = p3; H = 128; break;
        case 4: feat = p4; H = 64;  break;
        default: feat = p5; H = 32; break;
    }
    const int W = H;

    const float inv_r = 1.0f / (rows - 1.0f);
    const float inv_c = 1.0f / (cols - 1.0f);
    const float ny1 = y1 * inv_r;
    const float ny2 = y2 * inv_r;
    const float nx1 = x1 * inv_c;
    const float nx2 = x2 * inv_c;
    const float dny = ny2 - ny1;
    const float dnx = nx2 - nx1;
    const float Hm1 = (float)(H - 1);
    const float Wm1 = (float)(W - 1);

    const int t      = threadIdx.x;
    const int lane_c = t & (CH4 - 1);   // float4 channel index 0..63
    const int sgrp   = t >> 6;          // sample group 0..3

    const float4* __restrict__ f4 = (const float4*)feat;
    float4* __restrict__ o4 = (float4*)out + (size_t)box * (EXTENT * EXTENT * CH4);

    for (int s = sgrp; s < EXTENT * EXTENT; s += 4) {
        const int gy = s / EXTENT;
        const int gx = s - gy * EXTENT;

        const float gyf = (float)gy / (float)(EXTENT - 1);
        const float gxf = (float)gx / (float)(EXTENT - 1);

        const float ys = (ny1 + dny * gyf) * Hm1;
        const float xs = (nx1 + dnx * gxf) * Wm1;

        const float y0f = fminf(fmaxf(floorf(ys), 0.0f), (float)(H - 2));
        const float x0f = fminf(fmaxf(floorf(xs), 0.0f), (float)(W - 2));
        const int y0 = (int)y0f;
        const int x0 = (int)x0f;
        const float wy = ys - y0f;
        const float wx = xs - x0f;

        const float w00 = (1.0f - wy) * (1.0f - wx);
        const float w01 = (1.0f - wy) * wx;
        const float w10 = wy * (1.0f - wx);
        const float w11 = wy * wx;

        const size_t b00 = ((size_t)y0 * W + x0) * CH4 + lane_c;

        const float4 f00 = __ldg(&f4[b00]);
        const float4 f01 = __ldg(&f4[b00 + CH4]);
        const float4 f10 = __ldg(&f4[b00 + (size_t)W * CH4]);
        const float4 f11 = __ldg(&f4[b00 + (size_t)W * CH4 + CH4]);

        float4 r;
        r.x = f00.x * w00 + f01.x * w01 + f10.x * w10 + f11.x * w11;
        r.y = f00.y * w00 + f01.y * w01 + f10.y * w10 + f11.y * w11;
        r.z = f00.z * w00 + f01.z * w01 + f10.z * w10 + f11.z * w11;
        r.w = f00.w * w00 + f01.w * w01 + f10.w * w10 + f11.w * w11;

        o4[s * CH4 + lane_c] = r;
    }
}

extern "C" void kernel_launch(void* const* d_in, const int* in_sizes, int n_in,
                              void* d_out, int out_size)
{
    const float* metadata = (const float*)d_in[0];
    const float* boxes    = (const float*)d_in[1];
    const float* p2       = (const float*)d_in[2];
    const float* p3       = (const float*)d_in[3];
    const float* p4       = (const float*)d_in[4];
    const float* p5       = (const float*)d_in[5];
    float* out = (float*)d_out;

    roi_align_pyramid_kernel<<<NBOX, 256>>>(metadata, boxes, p2, p3, p4, p5, out);
}